// round 6
// baseline (speedup 1.0000x reference)
#include <cuda_runtime.h>

#define BB 128
#define TT 1024
#define VV 192
#define NTHREADS 384
#define NWARPS 12
#define NG 16            // row groups
#define RR 12            // rows per group
#define NC 8             // columns per thread
#define RSTRIDE 20       // region stride (floats): 16 regions hit 8 bank-quads x2 -> 2-wf floor

__device__ __forceinline__ void ffma2(unsigned long long& acc,
                                      unsigned long long a, unsigned long long b) {
    asm("fma.rn.f32x2 %0, %1, %2, %0;" : "+l"(acc) : "l"(a), "l"(b));
}
__device__ __forceinline__ unsigned long long pack2(float lo, float hi) {
    unsigned long long r;
    asm("mov.b64 %0, {%1, %2};" : "=l"(r) : "f"(lo), "f"(hi));
    return r;
}
__device__ __forceinline__ void unpack2(unsigned long long v, float& lo, float& hi) {
    asm("mov.b64 {%0, %1}, %2;" : "=f"(lo), "=f"(hi) : "l"(v));
}

__global__ __launch_bounds__(NTHREADS, 1)
void crf_loss_kernel(const float* __restrict__ em,
                     const int* __restrict__ tags,
                     const int* __restrict__ mask,
                     const float* __restrict__ trans,
                     const float* __restrict__ start_t,
                     const float* __restrict__ end_t,
                     float* __restrict__ out)
{
    __shared__ __align__(16) float s_p[2][NG * RSTRIDE];  // padded p, double-buffered
    __shared__ float s_d[4];                               // normalizer ring (2-step-lag writes)
    __shared__ int   s_mask[TT];
    __shared__ float s_red[NWARPS];
    __shared__ int   s_ired[NWARPS];
    __shared__ float s_num;
    __shared__ float s_seqlen;

    const int b    = blockIdx.x;
    const int tid  = threadIdx.x;
    const int lane = tid & 31;
    const int wid  = tid >> 5;
    const int jb   = tid >> 4;        // 0..23 : block of 8 columns
    const int grp  = tid & 15;        // 0..15 : row group (12 rows)
    const int jown = jb * NC + (grp >> 1);          // column this lane co-owns (dup x2)
    const bool writer = ((grp & 1) == 0);
    const int sts_off = (jown / RR) * RSTRIDE + (jown % RR);
    const bool g3 = (grp & 8), g2 = (grp & 4), g1 = (grp & 2);

    const float* emB = em   + (size_t)b * TT * VV;
    const int*   tgB = tags + (size_t)b * TT;
    const int*   mkB = mask + (size_t)b * TT;

    // ---------------- expT tile into registers: 8 cols x 12 rows, row-pair packed ----------------
    unsigned long long col2[NC * 6];   // col2[c*6+k] = (expT[i,j], expT[i+1,j]), i = grp*12+2k
    #pragma unroll
    for (int c = 0; c < NC; c++) {
        const int j = jb * NC + c;
        #pragma unroll
        for (int k = 0; k < 6; k++) {
            const int i = grp * RR + 2 * k;
            float e0 = __expf(trans[(i    ) * VV + j]);
            float e1 = __expf(trans[(i + 1) * VV + j]);
            col2[c * 6 + k] = pack2(e0, e1);
        }
    }

    // ---------------- mask to smem ----------------
    for (int t = tid; t < TT; t += NTHREADS) s_mask[t] = mkB[t];

    // ---------------- gold score + mask sum ----------------
    float gsum = 0.f;
    int   msum = 0;
    for (int t = tid; t < TT; t += NTHREADS) {
        int mk = mkB[t];
        msum += mk;
        if (t >= 1 && mk) {
            int tg = tgB[t];
            int tp = tgB[t - 1];
            gsum += emB[t * VV + tg] + trans[tp * VV + tg];
        }
    }
    #pragma unroll
    for (int o = 16; o > 0; o >>= 1) {
        gsum += __shfl_xor_sync(0xffffffffu, gsum, o);
        msum += __shfl_xor_sync(0xffffffffu, msum, o);
    }
    if (lane == 0) { s_red[wid] = gsum; s_ired[wid] = msum; }
    __syncthreads();
    if (tid == 0) {
        float g = 0.f; int mtot = 0;
        #pragma unroll
        for (int w = 0; w < NWARPS; w++) { g += s_red[w]; mtot += s_ired[w]; }
        int tag0  = tgB[0];
        float num = start_t[tag0] + emB[tag0] + g;
        int last  = mtot - 1; if (last < 0) last = 0;
        num += end_t[tgB[last]];
        s_num    = num;
        s_seqlen = fmaxf((float)mtot, 1.0f);
    }

    // ---------------- init: alpha0, block max M0, p0 ----------------
    float a0 = start_t[jown] + emB[jown];
    float wm = a0;
    #pragma unroll
    for (int o = 16; o > 0; o >>= 1)
        wm = fmaxf(wm, __shfl_xor_sync(0xffffffffu, wm, o));
    __syncthreads();                       // protect s_red (tid0 reading above)
    if (lane == 0) s_red[wid] = wm;
    __syncthreads();
    float M = s_red[0];
    #pragma unroll
    for (int w = 1; w < NWARPS; w++) M = fmaxf(M, s_red[w]);

    float p_reg = __expf(a0 - M);
    if (writer) s_p[0][sts_off] = p_reg;

    float beta0 = a0 - M;                  // tid0: log p of column 0 (tid0 owns jown=0)
    if (tid == 0) { s_d[1] = beta0; s_d[2] = beta0; }

    // emission prefetch, depth 2
    float e_n1 = emB[VV + jown];
    float e_n2 = emB[2 * VV + jown];

    // tid0 stash of previous step
    float s_save = 0.f, emit_save = 0.f, d_save = 0.f;
    int   mk_save = 1;

    // ---------------- forward recursion: ONE sync per step ----------------
    #pragma unroll 2
    for (int t = 1; t < TT; t++) {
        const int cur = (t - 1) & 1, nxt = t & 1;
        __syncthreads();

        const float d = s_d[t & 3];

        // deferred normalizer estimator (tid0, off the barrier-gating path):
        // predict d_{t+1} from step t-1's result, write 1 slot ahead.
        if (tid == 0 && t >= 2) {
            float lr = __logf(s_save) + emit_save;
            float nb = mk_save ? (lr - d_save) : (beta0 - d_save);
            float g  = nb - beta0 + d_save;            // true growth of step t-1 (0 if masked)
            s_d[(t + 1) & 3] = nb + 2.f * g - d;
            beta0 = nb;
        }

        const int   mk     = s_mask[t];
        const float emit_c = e_n1;
        e_n1 = e_n2;
        {
            int tn = (t + 2 < TT) ? (t + 2) : (TT - 1);
            e_n2 = emB[tn * VV + jown];
        }
        const float arg = mk ? (emit_c - d) : (-d);
        const float w_f = __expf(arg);

        // 8-col x 12-row matvec tile
        const double2* p2 = (const double2*)(s_p[cur] + grp * RSTRIDE);
        unsigned long long ac[NC];
        #pragma unroll
        for (int c = 0; c < NC; c++) ac[c] = 0ull;
        #pragma unroll
        for (int q = 0; q < 3; q++) {
            double2 v = p2[q];
            unsigned long long vx = __double_as_longlong(v.x);  // rows grp*12+4q, +1
            unsigned long long vy = __double_as_longlong(v.y);  // rows grp*12+4q+2, +3
            #pragma unroll
            for (int c = 0; c < NC; c++) {
                ffma2(ac[c], vx, col2[c * 6 + 2 * q]);
                ffma2(ac[c], vy, col2[c * 6 + 2 * q + 1]);
            }
        }
        float vv[NC];
        #pragma unroll
        for (int c = 0; c < NC; c++) {
            float lo, hi; unpack2(ac[c], lo, hi); vv[c] = lo + hi;
        }

        // 4-stage butterfly reduce-scatter over the 16 grp-lanes
        // stage 1 (xor 8): keep upper half of cols on high lanes
        float q0 = g3 ? vv[0] : vv[4];
        float q1 = g3 ? vv[1] : vv[5];
        float q2 = g3 ? vv[2] : vv[6];
        float q3 = g3 ? vv[3] : vv[7];
        float r0 = __shfl_xor_sync(0xffffffffu, q0, 8);
        float r1 = __shfl_xor_sync(0xffffffffu, q1, 8);
        float r2 = __shfl_xor_sync(0xffffffffu, q2, 8);
        float r3 = __shfl_xor_sync(0xffffffffu, q3, 8);
        float w0 = (g3 ? vv[4] : vv[0]) + r0;
        float w1 = (g3 ? vv[5] : vv[1]) + r1;
        float w2 = (g3 ? vv[6] : vv[2]) + r2;
        float w3 = (g3 ? vv[7] : vv[3]) + r3;
        // stage 2 (xor 4)
        float u0 = g2 ? w0 : w2;
        float u1 = g2 ? w1 : w3;
        float z0 = __shfl_xor_sync(0xffffffffu, u0, 4);
        float z1 = __shfl_xor_sync(0xffffffffu, u1, 4);
        float x0 = (g2 ? w2 : w0) + z0;
        float x1 = (g2 ? w3 : w1) + z1;
        // stage 3 (xor 2)
        float u2 = g1 ? x0 : x1;
        float z2 = __shfl_xor_sync(0xffffffffu, u2, 2);
        float y  = (g1 ? x1 : x0) + z2;
        // stage 4 (xor 1): both partners end with the full column sum
        float s  = y + __shfl_xor_sync(0xffffffffu, y, 1);

        float p_new = (mk ? s : p_reg) * w_f;
        p_reg = p_new;
        M += d;
        if (writer) s_p[nxt][sts_off] = p_new;

        // stash for tid0's deferred estimator (uniform, cheap)
        s_save = s; emit_save = emit_c; mk_save = mk; d_save = d;
    }

    // ---------------- final lse(alpha + end_trans) ----------------
    __syncthreads();
    float beta = __logf(p_reg);
    float v = writer ? (beta + end_t[jown]) : -3.0e38f;
    float wm2 = v;
    #pragma unroll
    for (int o = 16; o > 0; o >>= 1)
        wm2 = fmaxf(wm2, __shfl_xor_sync(0xffffffffu, wm2, o));
    if (lane == 0) s_red[wid] = wm2;
    __syncthreads();
    float m2 = s_red[0];
    #pragma unroll
    for (int w = 1; w < NWARPS; w++) m2 = fmaxf(m2, s_red[w]);

    float e = writer ? __expf(v - m2) : 0.f;
    #pragma unroll
    for (int o = 16; o > 0; o >>= 1)
        e += __shfl_xor_sync(0xffffffffu, e, o);
    __syncthreads();
    if (lane == 0) s_red[wid] = e;
    __syncthreads();

    if (tid == 0) {
        float ssum = 0.f;
        #pragma unroll
        for (int w = 0; w < NWARPS; w++) ssum += s_red[w];
        float logden = M + m2 + logf(ssum + 1e-8f);
        out[b] = (logden - s_num) / s_seqlen;
    }
}

extern "C" void kernel_launch(void* const* d_in, const int* in_sizes, int n_in,
                              void* d_out, int out_size)
{
    const float* em    = (const float*)d_in[0];
    const int*   tags  = (const int*)d_in[1];
    const int*   mask  = (const int*)d_in[2];
    const float* trans = (const float*)d_in[3];
    const float* st    = (const float*)d_in[4];
    const float* en    = (const float*)d_in[5];
    float* out = (float*)d_out;

    crf_loss_kernel<<<BB, NTHREADS>>>(em, tags, mask, trans, st, en, out);
}

// round 7
// speedup vs baseline: 1.1235x; 1.1235x over previous
#include <cuda_runtime.h>

#define BB 128
#define TT 1024
#define VV 192
#define NTHREADS 384
#define NWARPS 12
#define NG 16            // row groups
#define RR 12            // rows per group
#define NC 8             // columns per thread
#define RSTRIDE 20       // region stride (floats)
#define NBLK 128         // 128 blocks x 8 steps = 1024 steps (t = 1..1024, 1024 is phantom)

__device__ __forceinline__ void ffma2(unsigned long long& acc,
                                      unsigned long long a, unsigned long long b) {
    asm("fma.rn.f32x2 %0, %1, %2, %0;" : "+l"(acc) : "l"(a), "l"(b));
}
__device__ __forceinline__ unsigned long long pack2(float lo, float hi) {
    unsigned long long r;
    asm("mov.b64 %0, {%1, %2};" : "=l"(r) : "f"(lo), "f"(hi));
    return r;
}
__device__ __forceinline__ void unpack2(unsigned long long v, float& lo, float& hi) {
    asm("mov.b64 {%0, %1}, %2;" : "=f"(lo), "=f"(hi) : "l"(v));
}

__global__ __launch_bounds__(NTHREADS, 1)
void crf_loss_kernel(const float* __restrict__ em,
                     const int* __restrict__ tags,
                     const int* __restrict__ mask,
                     const float* __restrict__ trans,
                     const float* __restrict__ start_t,
                     const float* __restrict__ end_t,
                     float* __restrict__ out)
{
    __shared__ __align__(16) float s_p[2][NG * RSTRIDE];  // padded p, double-buffered
    __shared__ float s_d[2];                               // per-8-step-block normalizer
    __shared__ int   s_mask[TT];
    __shared__ float s_red[NWARPS];
    __shared__ int   s_ired[NWARPS];
    __shared__ float s_num;
    __shared__ float s_seqlen;

    const int b    = blockIdx.x;
    const int tid  = threadIdx.x;
    const int lane = tid & 31;
    const int wid  = tid >> 5;
    const int jb   = tid >> 4;        // 0..23 : block of 8 columns
    const int grp  = tid & 15;        // 0..15 : row group (12 rows)
    const int jown = jb * NC + (grp >> 1);          // column this lane co-owns (dup x2)
    const bool writer = ((grp & 1) == 0);
    const int sts_off = (jown / RR) * RSTRIDE + (jown % RR);
    const bool g3 = (grp & 8), g2 = (grp & 4), g1 = (grp & 2);

    const float* emB = em   + (size_t)b * TT * VV;
    const int*   tgB = tags + (size_t)b * TT;
    const int*   mkB = mask + (size_t)b * TT;

    // ---------------- expT tile into registers: 8 cols x 12 rows, row-pair packed ----------------
    unsigned long long col2[NC * 6];
    #pragma unroll
    for (int c = 0; c < NC; c++) {
        const int j = jb * NC + c;
        #pragma unroll
        for (int k = 0; k < 6; k++) {
            const int i = grp * RR + 2 * k;
            float e0 = __expf(trans[(i    ) * VV + j]);
            float e1 = __expf(trans[(i + 1) * VV + j]);
            col2[c * 6 + k] = pack2(e0, e1);
        }
    }

    // ---------------- mask to smem ----------------
    for (int t = tid; t < TT; t += NTHREADS) s_mask[t] = mkB[t];

    // ---------------- gold score + mask sum ----------------
    float gsum = 0.f;
    int   msum = 0;
    for (int t = tid; t < TT; t += NTHREADS) {
        int mk = mkB[t];
        msum += mk;
        if (t >= 1 && mk) {
            int tg = tgB[t];
            int tp = tgB[t - 1];
            gsum += emB[t * VV + tg] + trans[tp * VV + tg];
        }
    }
    #pragma unroll
    for (int o = 16; o > 0; o >>= 1) {
        gsum += __shfl_xor_sync(0xffffffffu, gsum, o);
        msum += __shfl_xor_sync(0xffffffffu, msum, o);
    }
    if (lane == 0) { s_red[wid] = gsum; s_ired[wid] = msum; }
    __syncthreads();
    if (tid == 0) {
        float g = 0.f; int mtot = 0;
        #pragma unroll
        for (int w = 0; w < NWARPS; w++) { g += s_red[w]; mtot += s_ired[w]; }
        int tag0  = tgB[0];
        float num = start_t[tag0] + emB[tag0] + g;
        int last  = mtot - 1; if (last < 0) last = 0;
        num += end_t[tgB[last]];
        s_num    = num;
        s_seqlen = fmaxf((float)mtot, 1.0f);
    }

    // ---------------- init: alpha0, block max M0, p0, sum S0 ----------------
    float a0 = start_t[jown] + emB[jown];
    float wm = a0;
    #pragma unroll
    for (int o = 16; o > 0; o >>= 1)
        wm = fmaxf(wm, __shfl_xor_sync(0xffffffffu, wm, o));
    __syncthreads();                       // protect s_red (tid0 reading above)
    if (lane == 0) s_red[wid] = wm;
    __syncthreads();
    float M = s_red[0];
    #pragma unroll
    for (int w = 1; w < NWARPS; w++) M = fmaxf(M, s_red[w]);

    float p_reg = __expf(a0 - M);
    if (writer) s_p[0][sts_off] = p_reg;

    // sum of p_init -> d0 estimate
    float ss = writer ? p_reg : 0.f;
    #pragma unroll
    for (int o = 16; o > 0; o >>= 1)
        ss += __shfl_xor_sync(0xffffffffu, ss, o);
    __syncthreads();
    if (lane == 0) s_red[wid] = ss;
    __syncthreads();
    if (tid == 0) {
        float S0 = 0.f;
        #pragma unroll
        for (int w = 0; w < NWARPS; w++) S0 += s_red[w];
        float d0v = __logf(S0 + 1e-30f);
        s_d[0] = d0v; s_d[1] = d0v;
    }
    __syncthreads();
    float d_cur = s_d[0];                  // normalizer for block 0
    float d_nxt = d_cur;

    // tid0 estimator state
    float beta_prev = a0 - M;              // log p0 at t=0 (tid0 owns col 0)
    float d_meas    = d_cur;               // normalizer active in the upcoming measured interval

    // emission/exp pipeline (for step t=1)
    float e1v = emB[VV + jown];            // emit t=1
    float e2v = emB[2 * VV + jown];        // emit t=2
    int   mk_cur = s_mask[1];
    float d_w   = d_cur;                   // d baked into w_cur
    float w_cur = __expf(mk_cur ? (e1v - d_w) : (-d_w));
    float e_n1 = e2v;                      // emit t=2
    float e_n2 = emB[3 * VV + jown];       // emit t=3

    // ---------------- forward recursion: 128 blocks x 8 steps, ONE sync per step ----------------
    #pragma unroll 1
    for (int tb = 0; tb < NBLK; tb++) {
        #pragma unroll
        for (int k = 0; k < 8; k++) {
            const int t   = 8 * tb + k + 1;
            const int cur = (t - 1) & 1, nxt = t & 1;
            __syncthreads();

            // once-per-block normalizer refresh (tid0, overlaps others' mat-vec)
            if (k == 0 && tid == 0 && tb >= 1) {
                float beta_now = __logf(p_reg);
                float g8 = beta_now - beta_prev + 8.f * d_meas;
                s_d[(tb + 1) & 1] = 0.125f * g8 + 0.03125f * beta_now;  // damped AR(2)
                beta_prev = beta_now;
                d_meas = d_cur;
            }

            // 8-col x 12-row matvec tile
            const double2* p2 = (const double2*)(s_p[cur] + grp * RSTRIDE);
            unsigned long long ac[NC];
            #pragma unroll
            for (int c = 0; c < NC; c++) ac[c] = 0ull;
            #pragma unroll
            for (int q = 0; q < 3; q++) {
                double2 v = p2[q];
                unsigned long long vx = __double_as_longlong(v.x);
                unsigned long long vy = __double_as_longlong(v.y);
                #pragma unroll
                for (int c = 0; c < NC; c++) {
                    ffma2(ac[c], vx, col2[c * 6 + 2 * q]);
                    ffma2(ac[c], vy, col2[c * 6 + 2 * q + 1]);
                }
            }
            float vv[NC];
            #pragma unroll
            for (int c = 0; c < NC; c++) {
                float lo, hi; unpack2(ac[c], lo, hi); vv[c] = lo + hi;
            }

            // 4-stage butterfly reduce-scatter over the 16 grp-lanes
            float q0 = g3 ? vv[0] : vv[4];
            float q1 = g3 ? vv[1] : vv[5];
            float q2 = g3 ? vv[2] : vv[6];
            float q3 = g3 ? vv[3] : vv[7];
            float r0 = __shfl_xor_sync(0xffffffffu, q0, 8);
            float r1 = __shfl_xor_sync(0xffffffffu, q1, 8);
            float r2 = __shfl_xor_sync(0xffffffffu, q2, 8);
            float r3 = __shfl_xor_sync(0xffffffffu, q3, 8);
            float w0 = (g3 ? vv[4] : vv[0]) + r0;
            float w1 = (g3 ? vv[5] : vv[1]) + r1;
            float w2 = (g3 ? vv[6] : vv[2]) + r2;
            float w3 = (g3 ? vv[7] : vv[3]) + r3;
            float u0 = g2 ? w0 : w2;
            float u1 = g2 ? w1 : w3;
            float z0 = __shfl_xor_sync(0xffffffffu, u0, 4);
            float z1 = __shfl_xor_sync(0xffffffffu, u1, 4);
            float x0 = (g2 ? w2 : w0) + z0;
            float x1 = (g2 ? w3 : w1) + z1;
            float u2 = g1 ? x0 : x1;
            float z2 = __shfl_xor_sync(0xffffffffu, u2, 2);
            float y  = (g1 ? x1 : x0) + z2;
            float s  = y + __shfl_xor_sync(0xffffffffu, y, 1);

            float p_new = (mk_cur ? s : p_reg) * w_cur;
            p_reg = p_new;
            M += d_w;
            if (writer) s_p[nxt][sts_off] = p_new;

            // ---- pre-work for step t+1 (before next barrier) ----
            if (k == 6) d_nxt = s_d[(tb + 1) & 1];
            const float d_use = (k == 7) ? d_nxt : d_cur;
            const int tnext = t + 1;
            const int mk_n  = (tnext < TT) ? s_mask[tnext] : 0;
            d_w   = d_use;
            w_cur = __expf(mk_n ? (e_n1 - d_use) : (-d_use));
            mk_cur = mk_n;
            e_n1 = e_n2;
            {
                int tn = (t + 3 < TT) ? (t + 3) : (TT - 1);
                e_n2 = emB[tn * VV + jown];
            }
            if (k == 7) d_cur = d_nxt;
        }
    }

    // ---------------- final lse(alpha + end_trans); alpha = M + log p ----------------
    __syncthreads();
    float beta = __logf(p_reg);
    float v = writer ? (beta + end_t[jown]) : -3.0e38f;
    float wm2 = v;
    #pragma unroll
    for (int o = 16; o > 0; o >>= 1)
        wm2 = fmaxf(wm2, __shfl_xor_sync(0xffffffffu, wm2, o));
    if (lane == 0) s_red[wid] = wm2;
    __syncthreads();
    float m2 = s_red[0];
    #pragma unroll
    for (int w = 1; w < NWARPS; w++) m2 = fmaxf(m2, s_red[w]);

    float e = writer ? __expf(v - m2) : 0.f;
    #pragma unroll
    for (int o = 16; o > 0; o >>= 1)
        e += __shfl_xor_sync(0xffffffffu, e, o);
    __syncthreads();
    if (lane == 0) s_red[wid] = e;
    __syncthreads();

    if (tid == 0) {
        float ssum = 0.f;
        #pragma unroll
        for (int w = 0; w < NWARPS; w++) ssum += s_red[w];
        float logden = M + m2 + logf(ssum + 1e-8f);
        out[b] = (logden - s_num) / s_seqlen;
    }
}

extern "C" void kernel_launch(void* const* d_in, const int* in_sizes, int n_in,
                              void* d_out, int out_size)
{
    const float* em    = (const float*)d_in[0];
    const int*   tags  = (const int*)d_in[1];
    const int*   mask  = (const int*)d_in[2];
    const float* trans = (const float*)d_in[3];
    const float* st    = (const float*)d_in[4];
    const float* en    = (const float*)d_in[5];
    float* out = (float*)d_out;

    crf_loss_kernel<<<BB, NTHREADS>>>(em, tags, mask, trans, st, en, out);
}

// round 8
// speedup vs baseline: 1.4181x; 1.2621x over previous
#include <cuda_runtime.h>

#define BB 128
#define TT 1024
#define VV 192
#define NTHREADS 384
#define NWARPS 12
#define NG 8             // row groups
#define RR 24            // rows per group
#define NC 4             // columns per thread
#define RSTRIDE 28       // region stride (floats): 8 regions hit distinct 16B bank-groups
#define NBLK 128         // 128 blocks x 8 steps

__device__ __forceinline__ void ffma2(unsigned long long& acc,
                                      unsigned long long a, unsigned long long b) {
    asm("fma.rn.f32x2 %0, %1, %2, %0;" : "+l"(acc) : "l"(a), "l"(b));
}
__device__ __forceinline__ unsigned long long pack2(float lo, float hi) {
    unsigned long long r;
    asm("mov.b64 %0, {%1, %2};" : "=l"(r) : "f"(lo), "f"(hi));
    return r;
}
__device__ __forceinline__ void unpack2(unsigned long long v, float& lo, float& hi) {
    asm("mov.b64 {%0, %1}, %2;" : "=f"(lo), "=f"(hi) : "l"(v));
}

__global__ __launch_bounds__(NTHREADS, 1)
void crf_loss_kernel(const float* __restrict__ em,
                     const int* __restrict__ tags,
                     const int* __restrict__ mask,
                     const float* __restrict__ trans,
                     const float* __restrict__ start_t,
                     const float* __restrict__ end_t,
                     float* __restrict__ out)
{
    __shared__ __align__(16) float s_p[2][NG * RSTRIDE];  // padded p, double-buffered
    __shared__ float s_d[2];                               // per-8-step-block normalizer
    __shared__ unsigned s_mbits[34];                       // mask bitset (1024 bits + pad)
    __shared__ float s_red[NWARPS];
    __shared__ int   s_ired[NWARPS];
    __shared__ float s_num;
    __shared__ float s_seqlen;

    const int b    = blockIdx.x;
    const int tid  = threadIdx.x;
    const int lane = tid & 31;
    const int wid  = tid >> 5;
    const int jb   = tid >> 3;        // 0..47 : block of 4 columns
    const int grp  = tid & 7;         // 0..7  : row group (24 rows)
    const int jown = jb * NC + (grp >> 1);          // column this lane co-owns (dup x2)
    const bool writer = ((grp & 1) == 0);
    const int sts_off = (jown / RR) * RSTRIDE + (jown % RR);
    const bool g2 = (grp & 4), g1 = (grp & 2);

    const float* emB = em   + (size_t)b * TT * VV;
    const int*   tgB = tags + (size_t)b * TT;
    const int*   mkB = mask + (size_t)b * TT;

    // ---------------- expT tile into registers: 4 cols x 24 rows, row-pair packed ----------------
    unsigned long long col2[NC * 12];
    #pragma unroll
    for (int c = 0; c < NC; c++) {
        const int j = jb * NC + c;
        #pragma unroll
        for (int k = 0; k < 12; k++) {
            const int i = grp * RR + 2 * k;
            float e0 = __expf(trans[(i    ) * VV + j]);
            float e1 = __expf(trans[(i + 1) * VV + j]);
            col2[c * 12 + k] = pack2(e0, e1);
        }
    }

    // ---------------- mask bitset via ballot ----------------
    for (int w = wid; w < 32; w += NWARPS) {
        int mk = mkB[w * 32 + lane];
        unsigned bal = __ballot_sync(0xffffffffu, mk != 0);
        if (lane == 0) s_mbits[w] = bal;
    }
    if (tid < 2) s_mbits[32 + tid] = 0u;

    // ---------------- gold score + mask sum ----------------
    float gsum = 0.f;
    int   msum = 0;
    for (int t = tid; t < TT; t += NTHREADS) {
        int mk = mkB[t];
        msum += mk;
        if (t >= 1 && mk) {
            int tg = tgB[t];
            int tp = tgB[t - 1];
            gsum += emB[t * VV + tg] + trans[tp * VV + tg];
        }
    }
    #pragma unroll
    for (int o = 16; o > 0; o >>= 1) {
        gsum += __shfl_xor_sync(0xffffffffu, gsum, o);
        msum += __shfl_xor_sync(0xffffffffu, msum, o);
    }
    if (lane == 0) { s_red[wid] = gsum; s_ired[wid] = msum; }
    __syncthreads();
    if (tid == 0) {
        float g = 0.f; int mtot = 0;
        #pragma unroll
        for (int w = 0; w < NWARPS; w++) { g += s_red[w]; mtot += s_ired[w]; }
        int tag0  = tgB[0];
        float num = start_t[tag0] + emB[tag0] + g;
        int last  = mtot - 1; if (last < 0) last = 0;
        num += end_t[tgB[last]];
        s_num    = num;
        s_seqlen = fmaxf((float)mtot, 1.0f);
    }

    // ---------------- init: alpha0, block max M0, p0, sum S0 ----------------
    float a0 = start_t[jown] + emB[jown];
    float wm = a0;
    #pragma unroll
    for (int o = 16; o > 0; o >>= 1)
        wm = fmaxf(wm, __shfl_xor_sync(0xffffffffu, wm, o));
    __syncthreads();                       // protect s_red
    if (lane == 0) s_red[wid] = wm;
    __syncthreads();
    float M = s_red[0];
    #pragma unroll
    for (int w = 1; w < NWARPS; w++) M = fmaxf(M, s_red[w]);

    float p_reg = __expf(a0 - M);
    if (writer) s_p[0][sts_off] = p_reg;

    // sum of p_init -> d0 estimate
    float ssum0 = writer ? p_reg : 0.f;
    #pragma unroll
    for (int o = 16; o > 0; o >>= 1)
        ssum0 += __shfl_xor_sync(0xffffffffu, ssum0, o);
    __syncthreads();
    if (lane == 0) s_red[wid] = ssum0;
    __syncthreads();
    if (tid == 0) {
        float S0 = 0.f;
        #pragma unroll
        for (int w = 0; w < NWARPS; w++) S0 += s_red[w];
        float d0v = __logf(S0 + 1e-30f);
        s_d[0] = d0v; s_d[1] = d0v;
    }
    __syncthreads();
    float d_cur = s_d[0];
    float d_nxt = d_cur;

    // tid0 estimator state (tid0 owns column 0, writer)
    float beta_prev = a0 - M;
    float d_meas    = d_cur;

    // mask window (64-bit, covers bits [wbase, wbase+63])
    int wbase = 0;
    unsigned long long mwin =
        (unsigned long long)s_mbits[0] | ((unsigned long long)s_mbits[1] << 32);

    // emission/exp pipeline for step t=1
    int   mk_cur = (int)((mwin >> 1) & 1ull);
    float d_w    = d_cur;
    float w_cur  = __expf(mk_cur ? (emB[VV + jown] - d_w) : (-d_w));
    float e_n1 = emB[2 * VV + jown];       // emit t=2
    float e_n2 = emB[3 * VV + jown];       // emit t=3

    // ---------------- forward recursion: 128 blocks x 8 steps, ONE sync per step ----------------
    #pragma unroll 1
    for (int tb = 0; tb < NBLK; tb++) {
        #pragma unroll
        for (int k = 0; k < 8; k++) {
            const int t   = 8 * tb + k + 1;
            const int cur = (t - 1) & 1, nxt = t & 1;
            __syncthreads();

            // once-per-block normalizer refresh (tid0, overlaps others' mat-vec)
            if (k == 0 && tid == 0 && tb >= 1) {
                float beta_now = __logf(p_reg);
                float g8 = beta_now - beta_prev + 8.f * d_meas;
                s_d[(tb + 1) & 1] = 0.125f * g8 + 0.03125f * beta_now;  // damped AR(2)
                beta_prev = beta_now;
                d_meas = d_cur;
            }

            // 4-col x 24-row matvec tile
            const double2* p2 = (const double2*)(s_p[cur] + grp * RSTRIDE);
            unsigned long long ac0 = 0ull, ac1 = 0ull, ac2 = 0ull, ac3 = 0ull;
            #pragma unroll
            for (int q = 0; q < 6; q++) {
                double2 v = p2[q];
                unsigned long long vx = __double_as_longlong(v.x);  // rows 4q, 4q+1
                unsigned long long vy = __double_as_longlong(v.y);  // rows 4q+2, 4q+3
                ffma2(ac0, vx, col2[ 0 + 2 * q]); ffma2(ac0, vy, col2[ 0 + 2 * q + 1]);
                ffma2(ac1, vx, col2[12 + 2 * q]); ffma2(ac1, vy, col2[12 + 2 * q + 1]);
                ffma2(ac2, vx, col2[24 + 2 * q]); ffma2(ac2, vy, col2[24 + 2 * q + 1]);
                ffma2(ac3, vx, col2[36 + 2 * q]); ffma2(ac3, vy, col2[36 + 2 * q + 1]);
            }
            float lo, hi;
            unpack2(ac0, lo, hi); float v0 = lo + hi;
            unpack2(ac1, lo, hi); float v1 = lo + hi;
            unpack2(ac2, lo, hi); float v2 = lo + hi;
            unpack2(ac3, lo, hi); float v3 = lo + hi;

            // 3-stage butterfly reduce-scatter over the 8 grp-lanes
            // stage 1 (xor 4): g2=0 keeps cols {0,1}, g2=1 keeps {2,3}
            float x0 = g2 ? v0 : v2;
            float x1 = g2 ? v1 : v3;
            float r0 = __shfl_xor_sync(0xffffffffu, x0, 4);
            float r1 = __shfl_xor_sync(0xffffffffu, x1, 4);
            float w0 = (g2 ? v2 : v0) + r0;
            float w1 = (g2 ? v3 : v1) + r1;
            // stage 2 (xor 2)
            float y  = g1 ? w0 : w1;
            float z  = __shfl_xor_sync(0xffffffffu, y, 2);
            float r  = (g1 ? w1 : w0) + z;
            // stage 3 (xor 1): both partners get the full column sum
            float s  = r + __shfl_xor_sync(0xffffffffu, r, 1);

            float p_new = (mk_cur ? s : p_reg) * w_cur;
            p_reg = p_new;
            M += d_w;
            if (writer) s_p[nxt][sts_off] = p_new;

            // ---- pre-work for step t+1 (before next barrier) ----
            if (k == 6) d_nxt = s_d[(tb + 1) & 1];
            const float d_use = (k == 7) ? d_nxt : d_cur;
            const int tnext = t + 1;
            const int mk_n  = (tnext < TT)
                            ? (int)((mwin >> (unsigned)(tnext - wbase)) & 1ull) : 0;
            d_w   = d_use;
            w_cur = __expf(mk_n ? (e_n1 - d_use) : (-d_use));
            mk_cur = mk_n;
            e_n1 = e_n2;
            {
                int tn = (t + 3 < TT) ? (t + 3) : (TT - 1);
                e_n2 = emB[tn * VV + jown];
            }
            if (k == 7) {
                d_cur = d_nxt;
                int a = (8 * (tb + 1) + 1) >> 5;     // window for next block
                wbase = a << 5;
                mwin = (unsigned long long)s_mbits[a]
                     | ((unsigned long long)s_mbits[a + 1] << 32);
            }
        }
    }

    // ---------------- final lse(alpha + end_trans); alpha = M + log p ----------------
    __syncthreads();
    float beta = __logf(p_reg);
    float v = writer ? (beta + end_t[jown]) : -3.0e38f;
    float wm2 = v;
    #pragma unroll
    for (int o = 16; o > 0; o >>= 1)
        wm2 = fmaxf(wm2, __shfl_xor_sync(0xffffffffu, wm2, o));
    if (lane == 0) s_red[wid] = wm2;
    __syncthreads();
    float m2 = s_red[0];
    #pragma unroll
    for (int w = 1; w < NWARPS; w++) m2 = fmaxf(m2, s_red[w]);

    float e = writer ? __expf(v - m2) : 0.f;
    #pragma unroll
    for (int o = 16; o > 0; o >>= 1)
        e += __shfl_xor_sync(0xffffffffu, e, o);
    __syncthreads();
    if (lane == 0) s_red[wid] = e;
    __syncthreads();

    if (tid == 0) {
        float ssum = 0.f;
        #pragma unroll
        for (int w = 0; w < NWARPS; w++) ssum += s_red[w];
        float logden = M + m2 + logf(ssum + 1e-8f);
        out[b] = (logden - s_num) / s_seqlen;
    }
}

extern "C" void kernel_launch(void* const* d_in, const int* in_sizes, int n_in,
                              void* d_out, int out_size)
{
    const float* em    = (const float*)d_in[0];
    const int*   tags  = (const int*)d_in[1];
    const int*   mask  = (const int*)d_in[2];
    const float* trans = (const float*)d_in[3];
    const float* st    = (const float*)d_in[4];
    const float* en    = (const float*)d_in[5];
    float* out = (float*)d_out;

    crf_loss_kernel<<<BB, NTHREADS>>>(em, tags, mask, trans, st, en, out);
}

// round 13
// speedup vs baseline: 1.4256x; 1.0053x over previous
#include <cuda_runtime.h>
#include <cuda_bf16.h>

#define BB 128
#define TT 1024
#define VV 192
#define NTHREADS 384
#define NWARPS 12
#define NG 8             // row groups
#define RR 24            // rows per group
#define NC 4             // columns per thread
#define PSTRIDE_B 80     // bytes per p-region (48B bf16 data + pad; 20g mod 32 banks distinct)
#define NBLK 128         // 128 blocks x 8 steps

__device__ __forceinline__ void hfma2(unsigned& acc, unsigned a, unsigned b) {
    asm("fma.rn.bf16x2 %0, %1, %2, %0;" : "+r"(acc) : "r"(a), "r"(b));
}
__device__ __forceinline__ unsigned pack_bf2(float lo, float hi) {
    unsigned r;
    asm("cvt.rn.bf16x2.f32 %0, %1, %2;" : "=r"(r) : "f"(hi), "f"(lo));
    return r;
}
__device__ __forceinline__ float bf_lo(unsigned v) { return __uint_as_float(v << 16); }
__device__ __forceinline__ float bf_hi(unsigned v) { return __uint_as_float(v & 0xffff0000u); }

__global__ __launch_bounds__(NTHREADS, 1)
void crf_loss_kernel(const float* __restrict__ em,
                     const int* __restrict__ tags,
                     const int* __restrict__ mask,
                     const float* __restrict__ trans,
                     const float* __restrict__ start_t,
                     const float* __restrict__ end_t,
                     float* __restrict__ out)
{
    __shared__ __align__(16) unsigned char s_praw[2][NG * PSTRIDE_B]; // bf16 p, double-buffered
    __shared__ float s_d[2];
    __shared__ unsigned s_mbits[34];
    __shared__ float s_red[NWARPS];
    __shared__ int   s_ired[NWARPS];
    __shared__ float s_num;
    __shared__ float s_seqlen;

    const int b    = blockIdx.x;
    const int tid  = threadIdx.x;
    const int lane = tid & 31;
    const int wid  = tid >> 5;
    const int jb   = tid >> 3;        // 0..47 : block of 4 columns
    const int grp  = tid & 7;         // 0..7  : row group (24 rows)
    const int jown = jb * NC + (grp >> 1);
    const bool writer = ((grp & 1) == 0);
    const bool g2 = (grp & 4), g1 = (grp & 2);

    const float* emB = em   + (size_t)b * TT * VV;
    const int*   tgB = tags + (size_t)b * TT;
    const int*   mkB = mask + (size_t)b * TT;

    unsigned char* pb0 = &s_praw[0][0];
    unsigned char* pb1 = &s_praw[1][0];
    unsigned char* sts0 = pb0 + (jown / RR) * PSTRIDE_B + (jown % RR) * 2;
    unsigned char* sts1 = pb1 + (jown / RR) * PSTRIDE_B + (jown % RR) * 2;

    // ---------------- expT tile: 4 cols x 24 rows, bf16x2 row-pairs ----------------
    unsigned col2h[NC * 12];
    #pragma unroll
    for (int c = 0; c < NC; c++) {
        const int j = jb * NC + c;
        #pragma unroll
        for (int k = 0; k < 12; k++) {
            const int i = grp * RR + 2 * k;
            float e0 = __expf(trans[(i    ) * VV + j]);
            float e1 = __expf(trans[(i + 1) * VV + j]);
            col2h[c * 12 + k] = pack_bf2(e0, e1);
        }
    }

    // ---------------- mask bitset via ballot ----------------
    for (int w = wid; w < 32; w += NWARPS) {
        int mk = mkB[w * 32 + lane];
        unsigned bal = __ballot_sync(0xffffffffu, mk != 0);
        if (lane == 0) s_mbits[w] = bal;
    }
    if (tid < 2) s_mbits[32 + tid] = 0u;

    // ---------------- gold score + mask sum ----------------
    float gsum = 0.f;
    int   msum = 0;
    for (int t = tid; t < TT; t += NTHREADS) {
        int mk = mkB[t];
        msum += mk;
        if (t >= 1 && mk) {
            int tg = tgB[t];
            int tp = tgB[t - 1];
            gsum += emB[t * VV + tg] + trans[tp * VV + tg];
        }
    }
    #pragma unroll
    for (int o = 16; o > 0; o >>= 1) {
        gsum += __shfl_xor_sync(0xffffffffu, gsum, o);
        msum += __shfl_xor_sync(0xffffffffu, msum, o);
    }
    if (lane == 0) { s_red[wid] = gsum; s_ired[wid] = msum; }
    __syncthreads();
    if (tid == 0) {
        float g = 0.f; int mtot = 0;
        #pragma unroll
        for (int w = 0; w < NWARPS; w++) { g += s_red[w]; mtot += s_ired[w]; }
        int tag0  = tgB[0];
        float num = start_t[tag0] + emB[tag0] + g;
        int last  = mtot - 1; if (last < 0) last = 0;
        num += end_t[tgB[last]];
        s_num    = num;
        s_seqlen = fmaxf((float)mtot, 1.0f);
    }

    // ---------------- init: alpha0, block max M0, p0, sum S0 ----------------
    float a0 = start_t[jown] + emB[jown];
    float wm = a0;
    #pragma unroll
    for (int o = 16; o > 0; o >>= 1)
        wm = fmaxf(wm, __shfl_xor_sync(0xffffffffu, wm, o));
    __syncthreads();                       // protect s_red
    if (lane == 0) s_red[wid] = wm;
    __syncthreads();
    float M = s_red[0];
    #pragma unroll
    for (int w = 1; w < NWARPS; w++) M = fmaxf(M, s_red[w]);

    float p_reg = __expf(a0 - M);
    if (writer) *(__nv_bfloat16*)sts0 = __float2bfloat16(p_reg);

    // sum of p_init -> d0 estimate
    float ssum0 = writer ? p_reg : 0.f;
    #pragma unroll
    for (int o = 16; o > 0; o >>= 1)
        ssum0 += __shfl_xor_sync(0xffffffffu, ssum0, o);
    __syncthreads();
    if (lane == 0) s_red[wid] = ssum0;
    __syncthreads();
    if (tid == 0) {
        float S0 = 0.f;
        #pragma unroll
        for (int w = 0; w < NWARPS; w++) S0 += s_red[w];
        float d0v = __logf(fmaxf(S0, 1e-30f));
        s_d[0] = d0v; s_d[1] = d0v;
    }
    __syncthreads();
    float d_cur = s_d[0];
    float d_nxt = d_cur;

    // tid0 estimator state (tid0 owns column 0, writer)
    float beta_prev = a0 - M;
    float d_meas    = d_cur;

    // mask window (64-bit, covers bits [wbase, wbase+63])
    int wbase = 0;
    unsigned long long mwin =
        (unsigned long long)s_mbits[0] | ((unsigned long long)s_mbits[1] << 32);

    // emission/exp pipeline for step t=1
    int   mk_cur = (int)((mwin >> 1) & 1ull);
    float d_w    = d_cur;
    float w_cur  = __expf(mk_cur ? (emB[VV + jown] - d_w) : (-d_w));
    float e_n1 = emB[2 * VV + jown];       // emit t=2
    float e_n2 = emB[3 * VV + jown];       // emit t=3

    // ---------------- forward recursion: 128 blocks x 8 steps, ONE sync per step ----------------
    #pragma unroll 1
    for (int tb = 0; tb < NBLK; tb++) {
        #pragma unroll
        for (int k = 0; k < 8; k++) {
            const int t = 8 * tb + k + 1;
            unsigned char* pcur = ((t - 1) & 1) ? pb1 : pb0;
            __syncthreads();

            // once-per-block normalizer refresh (tid0, overlaps others' matvec)
            if (k == 0 && tid == 0 && tb >= 1) {
                float beta_now = __logf(fmaxf(p_reg, 1e-35f));
                float g8 = beta_now - beta_prev + 8.f * d_meas;
                s_d[(tb + 1) & 1] = 0.125f * g8 + 0.03125f * beta_now;  // damped AR(2)
                beta_prev = beta_now;
                d_meas = d_cur;
            }

            // 4-col x 24-row bf16 matvec
            const uint4* p4 = (const uint4*)(pcur + grp * PSTRIDE_B);
            unsigned ac0 = 0u, ac1 = 0u, ac2 = 0u, ac3 = 0u;
            #pragma unroll
            for (int q = 0; q < 3; q++) {
                uint4 v = p4[q];
                hfma2(ac0, v.x, col2h[ 0 + 4 * q + 0]); hfma2(ac1, v.x, col2h[12 + 4 * q + 0]);
                hfma2(ac2, v.x, col2h[24 + 4 * q + 0]); hfma2(ac3, v.x, col2h[36 + 4 * q + 0]);
                hfma2(ac0, v.y, col2h[ 0 + 4 * q + 1]); hfma2(ac1, v.y, col2h[12 + 4 * q + 1]);
                hfma2(ac2, v.y, col2h[24 + 4 * q + 1]); hfma2(ac3, v.y, col2h[36 + 4 * q + 1]);
                hfma2(ac0, v.z, col2h[ 0 + 4 * q + 2]); hfma2(ac1, v.z, col2h[12 + 4 * q + 2]);
                hfma2(ac2, v.z, col2h[24 + 4 * q + 2]); hfma2(ac3, v.z, col2h[36 + 4 * q + 2]);
                hfma2(ac0, v.w, col2h[ 0 + 4 * q + 3]); hfma2(ac1, v.w, col2h[12 + 4 * q + 3]);
                hfma2(ac2, v.w, col2h[24 + 4 * q + 3]); hfma2(ac3, v.w, col2h[36 + 4 * q + 3]);
            }
            float v0 = bf_lo(ac0) + bf_hi(ac0);
            float v1 = bf_lo(ac1) + bf_hi(ac1);
            float v2 = bf_lo(ac2) + bf_hi(ac2);
            float v3 = bf_lo(ac3) + bf_hi(ac3);

            // 3-stage butterfly reduce-scatter over the 8 grp-lanes
            float x0 = g2 ? v0 : v2;
            float x1 = g2 ? v1 : v3;
            float r0 = __shfl_xor_sync(0xffffffffu, x0, 4);
            float r1 = __shfl_xor_sync(0xffffffffu, x1, 4);
            float w0 = (g2 ? v2 : v0) + r0;
            float w1 = (g2 ? v3 : v1) + r1;
            float y  = g1 ? w0 : w1;
            float z  = __shfl_xor_sync(0xffffffffu, y, 2);
            float r  = (g1 ? w1 : w0) + z;
            float s  = r + __shfl_xor_sync(0xffffffffu, r, 1);

            float p_new = (mk_cur ? s : p_reg) * w_cur;
            p_reg = p_new;
            M += d_w;
            if (writer) {
                unsigned char* psts = (t & 1) ? sts1 : sts0;
                *(__nv_bfloat16*)psts = __float2bfloat16(p_new);
            }

            // ---- pre-work for step t+1 (before next barrier) ----
            if (k == 6) d_nxt = s_d[(tb + 1) & 1];
            const float d_use = (k == 7) ? d_nxt : d_cur;
            const int tnext = t + 1;
            const int mk_n  = (tnext < TT)
                            ? (int)((mwin >> (unsigned)(tnext - wbase)) & 1ull) : 0;
            d_w   = d_use;
            w_cur = __expf(mk_n ? (e_n1 - d_use) : (-d_use));
            mk_cur = mk_n;
            e_n1 = e_n2;
            {
                int tn = (t + 3 < TT) ? (t + 3) : (TT - 1);
                e_n2 = emB[tn * VV + jown];
            }
            if (k == 7) {
                d_cur = d_nxt;
                int a = (8 * (tb + 1) + 1) >> 5;
                wbase = a << 5;
                mwin = (unsigned long long)s_mbits[a]
                     | ((unsigned long long)s_mbits[a + 1] << 32);
            }
        }
    }

    // ---------------- final lse(alpha + end_trans); alpha = M + log p ----------------
    __syncthreads();
    float beta = __logf(fmaxf(p_reg, 1e-35f));
    float v = writer ? (beta + end_t[jown]) : -3.0e38f;
    float wm2 = v;
    #pragma unroll
    for (int o = 16; o > 0; o >>= 1)
        wm2 = fmaxf(wm2, __shfl_xor_sync(0xffffffffu, wm2, o));
    if (lane == 0) s_red[wid] = wm2;
    __syncthreads();
    float m2 = s_red[0];
    #pragma unroll
    for (int w = 1; w < NWARPS; w++) m2 = fmaxf(m2, s_red[w]);

    float e = writer ? __expf(v - m2) : 0.f;
    #pragma unroll
    for (int o = 16; o > 0; o >>= 1)
        e += __shfl_xor_sync(0xffffffffu, e, o);
    __syncthreads();
    if (lane == 0) s_red[wid] = e;
    __syncthreads();

    if (tid == 0) {
        float ssum = 0.f;
        #pragma unroll
        for (int w = 0; w < NWARPS; w++) ssum += s_red[w];
        float logden = M + m2 + logf(ssum + 1e-8f);
        out[b] = (logden - s_num) / s_seqlen;
    }
}

extern "C" void kernel_launch(void* const* d_in, const int* in_sizes, int n_in,
                              void* d_out, int out_size)
{
    const float* em    = (const float*)d_in[0];
    const int*   tags  = (const int*)d_in[1];
    const int*   mask  = (const int*)d_in[2];
    const float* trans = (const float*)d_in[3];
    const float* st    = (const float*)d_in[4];
    const float* en    = (const float*)d_in[5];
    float* out = (float*)d_out;

    crf_loss_kernel<<<BB, NTHREADS>>>(em, tags, mask, trans, st, en, out);
}